// round 15
// baseline (speedup 1.0000x reference)
#include <cuda_runtime.h>
#include <cstdint>

#define T_DIM 12
#define V_DIM 200
#define PADQ  17      // float4/ulonglong2 per padded band row (16 data + 1 pad)
#define PADW  68      // floats per padded band row
#define PADE  53      // floats per e_s row (conflict-free transpose staging)

typedef unsigned long long u64;

// Partial column sums, flat-w layout: [nt(48)][band i(4)][w(200)]
__device__ __align__(16) float g_psum[48 * 4 * 200];
// Per-output-slab dependency counters (monotone, +16 per launch each).
__device__ unsigned g_done[48];

// ---------------------------------------------------------------------------
// Packed fp32x2 helpers (sm_100+)
// ---------------------------------------------------------------------------
__device__ __forceinline__ u64 padd2(u64 a, u64 b) {
    u64 r;
    asm("add.rn.f32x2 %0, %1, %2;" : "=l"(r) : "l"(a), "l"(b));
    return r;
}

__device__ __forceinline__ float2 unpack2(u64 v) {
    float2 r;
    asm("mov.b64 {%0, %1}, %2;" : "=f"(r.x), "=f"(r.y) : "l"(v));
    return r;
}

// ---------------------------------------------------------------------------
// Fused kernel: symmetric tile-pair compute + per-slab finisher normalization.
//
// Compute: s(v,w) = sum_f |y_v - y_w| (y = x*a, valid since a >= 0) is
// symmetric per input slab (n,t). Block (job, nt) handles band pair (i<=j),
// writes exp(s) to BOTH permuted output locations (transpose staged in smem)
// plus column partials into g_psum.
//
// Epilogue: output slab (np,t) depends on exactly 16 blocks (4 band-pairs
// touching np x 4 n). Each block, after fencing its writes, bumps g_done for
// the slab(s) it feeds; the 16th arrival normalizes that slab inline. No
// grid barrier, no spin - nothing to deadlock, co-residency not required.
//
// grid = (10, 48); block = 256; threads 0..249 = (wl 0..49, vg 0..4).
// ---------------------------------------------------------------------------
extern __shared__ unsigned char smem_raw[];

__global__ void __launch_bounds__(256, 4)
k_fused(const float* __restrict__ x, const float* __restrict__ a,
        float* __restrict__ out) {
    const int job = blockIdx.x;          // 0..9
    const int nt  = blockIdx.y;          // 0..47
    const int n   = nt / T_DIM;
    const int t   = nt % T_DIM;
    const int tid = threadIdx.x;

    // Decode (i,j), i<=j, from job index.
    int i, j;
    if (job < 4)      { i = 0; j = job; }
    else if (job < 7) { i = 1; j = job - 3; }
    else if (job < 9) { i = 2; j = job - 5; }
    else              { i = 3; j = 3; }

    float* ybi    = reinterpret_cast<float*>(smem_raw);      // [50*68]
    float* ybj    = ybi + 50 * PADW;                          // [50*68]
    float* e_s    = ybj + 50 * PADW;                          // [50*53]
    float* psum_s = e_s + 50 * PADE;                          // [250]
    int*   fin    = reinterpret_cast<int*>(psum_s + 250);     // [2]

    const float4* x4 = reinterpret_cast<const float4*>(
        x + (size_t)nt * V_DIM * 64);
    const float4* a4 = reinterpret_cast<const float4*>(a);
    const bool diag = (i == j);

    // Load + pre-scale bands (padded rows; valid since a >= 0).
    {
        const float4 ar = __ldg(&a4[tid & 15]);
        float4* ybi4 = reinterpret_cast<float4*>(ybi);
        float4* ybj4 = reinterpret_cast<float4*>(ybj);
        for (int idx = tid; idx < 800; idx += 256) {
            const int row = idx >> 4, fq = idx & 15;
            float4 v = x4[(i * 50 + row) * 16 + fq];
            v.x *= ar.x; v.y *= ar.y; v.z *= ar.z; v.w *= ar.w;
            ybi4[row * PADQ + fq] = v;
            if (!diag) {
                float4 u = x4[(j * 50 + row) * 16 + fq];
                u.x *= ar.x; u.y *= ar.y; u.z *= ar.z; u.w *= ar.w;
                ybj4[row * PADQ + fq] = u;
            }
        }
    }
    __syncthreads();

    const float* ybw = diag ? ybi : ybj;       // band holding the w columns
    const ulonglong2* yi2 = reinterpret_cast<const ulonglong2*>(ybi);
    const ulonglong2* yw2 = reinterpret_cast<const ulonglong2*>(ybw);

    const int wl = tid % 50;                   // w column within band j
    const int vg = tid / 50;                   // row group (0..4), vg==5 idle

    if (vg < 5) {
        const u64 NEG2 = 0x8000000080000000ULL;
        const u64 ABS2 = 0x7FFFFFFF7FFFFFFFULL;

        float rsum[10];
        #pragma unroll
        for (int l = 0; l < 10; l++) rsum[l] = 0.0f;

        const ulonglong2* ywbase = yw2 + wl * PADQ;
        const ulonglong2* yvbase = yi2 + (size_t)(vg * 10) * PADQ;

        #pragma unroll 1
        for (int pass = 0; pass < 4; pass++) {
            // Quarter ywn: 4 fq = 8 u64 = 16 regs.
            u64 ywn[8];
            #pragma unroll
            for (int fq = 0; fq < 4; fq++) {
                ulonglong2 r = ywbase[pass * 4 + fq];
                ywn[2 * fq]     = r.x ^ NEG2;
                ywn[2 * fq + 1] = r.y ^ NEG2;
            }

            const ulonglong2* rp = yvbase + pass * 4;
            #pragma unroll
            for (int l = 0; l < 10; l += 2) {
                u64 a00 = 0ULL, a01 = 0ULL, a10 = 0ULL, a11 = 0ULL;
                #pragma unroll
                for (int fq = 0; fq < 4; fq++) {
                    ulonglong2 q0 = rp[fq];            // broadcast LDS.128
                    ulonglong2 q1 = rp[PADQ + fq];
                    u64 d0a = padd2(q0.x, ywn[2 * fq])     & ABS2;
                    u64 d0b = padd2(q0.y, ywn[2 * fq + 1]) & ABS2;
                    u64 d1a = padd2(q1.x, ywn[2 * fq])     & ABS2;
                    u64 d1b = padd2(q1.y, ywn[2 * fq + 1]) & ABS2;
                    a00 = padd2(a00, d0a);
                    a01 = padd2(a01, d0b);
                    a10 = padd2(a10, d1a);
                    a11 = padd2(a11, d1b);
                }
                const float2 p0 = unpack2(padd2(a00, a01));
                const float2 p1 = unpack2(padd2(a10, a11));
                rsum[l]     += p0.x + p0.y;
                rsum[l + 1] += p1.x + p1.y;
                rp += 2 * PADQ;
            }
        }

        // Compute epilogue: exp + direct stores + transpose staging.
        float* opd = out + (((size_t)(i * T_DIM + t) * V_DIM)
                            + (vg * 10 * 4 + n)) * V_DIM + j * 50 + wl;
        float* esp = e_s + wl * PADE + vg * 10;
        float dsum = 0.0f;
        #pragma unroll
        for (int l = 0; l < 10; l++) {
            const float e = __expf(rsum[l]);
            opd[(size_t)l * 4 * V_DIM] = e;
            if (!diag) esp[l] = e;
            dsum += e;
        }
        psum_s[vg * 50 + wl] = dsum;
    }
    __syncthreads();

    // Direct column partials: slab i, w band j (flat-w psum layout).
    if (tid < 50) {
        const float s = psum_s[tid] + psum_s[50 + tid] + psum_s[100 + tid] +
                        psum_s[150 + tid] + psum_s[200 + tid];
        g_psum[((size_t)nt * 4 + i) * V_DIM + j * 50 + tid] = s;
    }

    if (!diag) {
        // Transposed writes: slab j, row wl*4+n, col i*50+vl (coalesced).
        float* outj = out + ((size_t)(j * T_DIM + t) * V_DIM) * V_DIM;
        #pragma unroll
        for (int k = tid; k < 2500; k += 256) {
            const int rw = k / 50;             // wl
            const int cv = k % 50;             // vl
            outj[(size_t)(rw * 4 + n) * V_DIM + i * 50 + cv] =
                e_s[rw * PADE + cv];
        }
        // Transposed column partials: slab j, w band i.
        if (tid < 50) {
            float s = 0.0f;
            #pragma unroll
            for (int rw = 0; rw < 50; rw++) s += e_s[rw * PADE + tid];
            g_psum[((size_t)nt * 4 + j) * V_DIM + i * 50 + tid] = s;
        }
    }

    // ---- publish writes, bump per-slab dependency counters ----
    __threadfence();                     // every thread fences its own writes
    __syncthreads();                     // all fences done before the bump
    if (tid == 0) {
        // Slab (np,t) has exactly 16 feeders per launch; monotone counters
        // (%16) stay replay-correct with no reset. 16th arrival = finisher.
        fin[0] = (int)(atomicAdd(&g_done[i * T_DIM + t], 1u) % 16u == 15u);
        fin[1] = diag ? 0
               : (int)(atomicAdd(&g_done[j * T_DIM + t], 1u) % 16u == 15u);
    }
    __syncthreads();

    // ---- finisher: normalize the slab(s) whose last feeder we were ----
    #pragma unroll
    for (int which = 0; which < 2; which++) {
        if (!fin[which]) continue;       // uniform (smem) -> no divergence
        const int np  = (which == 0) ? i : j;
        const int ntp = np * T_DIM + t;

        float* sinv = ybi;               // reuse band smem (done with it)
        if (tid < 50) {
            const float4* p4 = reinterpret_cast<const float4*>(g_psum);
            float4 s0 = p4[((size_t)(0 * T_DIM + t) * 4 + np) * 50 + tid];
            float4 s1 = p4[((size_t)(1 * T_DIM + t) * 4 + np) * 50 + tid];
            float4 s2 = p4[((size_t)(2 * T_DIM + t) * 4 + np) * 50 + tid];
            float4 s3 = p4[((size_t)(3 * T_DIM + t) * 4 + np) * 50 + tid];
            float4 r;
            r.x = 1.0f / ((s0.x + s1.x) + (s2.x + s3.x));
            r.y = 1.0f / ((s0.y + s1.y) + (s2.y + s3.y));
            r.z = 1.0f / ((s0.z + s1.z) + (s2.z + s3.z));
            r.w = 1.0f / ((s0.w + s1.w) + (s2.w + s3.w));
            reinterpret_cast<float4*>(sinv)[tid] = r;
        }
        __syncthreads();

        const float4* si4 = reinterpret_cast<const float4*>(sinv);
        float4* o4 = reinterpret_cast<float4*>(out)
                     + (size_t)ntp * (V_DIM * V_DIM / 4);
        for (int k = tid; k < 10000; k += 256) {
            float4 v = o4[k];
            const float4 m = si4[k % 50];
            v.x *= m.x; v.y *= m.y; v.z *= m.z; v.w *= m.w;
            o4[k] = v;
        }
        __syncthreads();                 // sinv reuse safety for which==1
    }
}

// ---------------------------------------------------------------------------

extern "C" void kernel_launch(void* const* d_in, const int* in_sizes, int n_in,
                              void* d_out, int out_size) {
    const float* x = (const float*)d_in[0];
    const float* a = (const float*)d_in[1];
    // Defensive input-order check: a has exactly F=64 elements.
    if (n_in >= 2 && in_sizes[0] == 64) {
        x = (const float*)d_in[1];
        a = (const float*)d_in[0];
    }
    float* out = (float*)d_out;

    // Smem: 2 padded bands + e_s tile + psum partials + finisher flags.
    const int smem_bytes =
        (2 * 50 * PADW + 50 * PADE + 250 + 2) * (int)sizeof(float);  // 39208
    cudaFuncSetAttribute(k_fused, cudaFuncAttributeMaxDynamicSharedMemorySize,
                         smem_bytes);

    dim3 g1(10, 48);                 // 480 tile-pair jobs
    k_fused<<<g1, 256, smem_bytes>>>(x, a, out);
}

// round 17
// speedup vs baseline: 1.5700x; 1.5700x over previous
#include <cuda_runtime.h>
#include <cstdint>

#define T_DIM 12
#define V_DIM 200
#define PADQ  17      // float4/ulonglong2 per padded band row (16 data + 1 pad)
#define PADW  68      // floats per padded band row
#define PADE  53      // floats per e_s row (conflict-free transpose staging)

typedef unsigned long long u64;

// Partial column sums: [nt(48)][slab i(4)][col band j(4)][wl(50)]
__device__ float g_psum[48 * 4 * 4 * 50];
// Reciprocal column sums per output slab: [ntp(48)][w(200)]
__device__ __align__(16) float g_sinv[48 * 200];

// ---------------------------------------------------------------------------
// Packed fp32x2 helpers (sm_100+)
// ---------------------------------------------------------------------------
__device__ __forceinline__ u64 padd2(u64 a, u64 b) {
    u64 r;
    asm("add.rn.f32x2 %0, %1, %2;" : "=l"(r) : "l"(a), "l"(b));
    return r;
}

__device__ __forceinline__ float2 unpack2(u64 v) {
    float2 r;
    asm("mov.b64 {%0, %1}, %2;" : "=f"(r.x), "=f"(r.y) : "l"(v));
    return r;
}

// ---------------------------------------------------------------------------
// Kernel 1: symmetric tile-pair compute; packed diff + scalar |abs|-fold acc.
//
// s(v,w) = sum_f |y_v - y_w| (y = x*a, valid since a >= 0) is symmetric per
// input slab (n,t). Inner body per fq: 2 LDS + 4 packed subs + 8 scalar
// FADD with free |operand| modifiers (the u64-AND abs and its 8 LOP3s are
// gone). Each block handles one band pair (i<=j) of the 4x4 partition into
// 50-row bands, writes exp(s) to BOTH permuted output locations (transpose
// staged via padded smem), plus column partials.
//
// grid = (10, 48); block = 256; threads 0..249 = (wl 0..49, vg 0..4).
// ---------------------------------------------------------------------------
extern __shared__ unsigned char smem_raw[];

__global__ void __launch_bounds__(256, 4)
k_compute(const float* __restrict__ x, const float* __restrict__ a,
          float* __restrict__ out) {
    const int job = blockIdx.x;          // 0..9
    const int nt  = blockIdx.y;          // 0..47
    const int n   = nt / T_DIM;
    const int t   = nt % T_DIM;
    const int tid = threadIdx.x;

    // Decode (i,j), i<=j, from job index.
    int i, j;
    if (job < 4)      { i = 0; j = job; }
    else if (job < 7) { i = 1; j = job - 3; }
    else if (job < 9) { i = 2; j = job - 5; }
    else              { i = 3; j = 3; }

    float* ybi    = reinterpret_cast<float*>(smem_raw);      // [50*68]
    float* ybj    = ybi + 50 * PADW;                          // [50*68]
    float* e_s    = ybj + 50 * PADW;                          // [50*53]
    float* psum_s = e_s + 50 * PADE;                          // [250]

    const float4* x4 = reinterpret_cast<const float4*>(
        x + (size_t)nt * V_DIM * 64);
    const float4* a4 = reinterpret_cast<const float4*>(a);
    const bool diag = (i == j);

    // Load + pre-scale bands (padded rows; valid since a >= 0).
    {
        const float4 ar = __ldg(&a4[tid & 15]);
        float4* ybi4 = reinterpret_cast<float4*>(ybi);
        float4* ybj4 = reinterpret_cast<float4*>(ybj);
        for (int idx = tid; idx < 800; idx += 256) {
            const int row = idx >> 4, fq = idx & 15;
            float4 v = x4[(i * 50 + row) * 16 + fq];
            v.x *= ar.x; v.y *= ar.y; v.z *= ar.z; v.w *= ar.w;
            ybi4[row * PADQ + fq] = v;
            if (!diag) {
                float4 u = x4[(j * 50 + row) * 16 + fq];
                u.x *= ar.x; u.y *= ar.y; u.z *= ar.z; u.w *= ar.w;
                ybj4[row * PADQ + fq] = u;
            }
        }
    }
    __syncthreads();

    const float* ybw = diag ? ybi : ybj;       // band holding the w columns
    const ulonglong2* yi2 = reinterpret_cast<const ulonglong2*>(ybi);
    const ulonglong2* yw2 = reinterpret_cast<const ulonglong2*>(ybw);

    const int wl = tid % 50;                   // w column within band j
    const int vg = tid / 50;                   // row group (0..4), vg==5 idle

    if (vg < 5) {
        const u64 NEG2 = 0x8000000080000000ULL;

        float rsum[10];
        #pragma unroll
        for (int l = 0; l < 10; l++) rsum[l] = 0.0f;

        const ulonglong2* ywbase = yw2 + wl * PADQ;
        const ulonglong2* yvbase = yi2 + (size_t)(vg * 10) * PADQ;

        #pragma unroll 1
        for (int pass = 0; pass < 4; pass++) {
            // Quarter ywn: 4 fq = 8 u64 = 16 regs (pre-negated).
            u64 ywn[8];
            #pragma unroll
            for (int fq = 0; fq < 4; fq++) {
                ulonglong2 r = ywbase[pass * 4 + fq];
                ywn[2 * fq]     = r.x ^ NEG2;
                ywn[2 * fq + 1] = r.y ^ NEG2;
            }

            const ulonglong2* rp = yvbase + pass * 4;
            #pragma unroll
            for (int l = 0; l < 10; l += 2) {
                float c0 = 0.f, c1 = 0.f, c2 = 0.f, c3 = 0.f;
                float c4 = 0.f, c5 = 0.f, c6 = 0.f, c7 = 0.f;
                #pragma unroll
                for (int fq = 0; fq < 4; fq++) {
                    ulonglong2 q0 = rp[fq];            // broadcast LDS.128
                    ulonglong2 q1 = rp[PADQ + fq];
                    const u64 d0a = padd2(q0.x, ywn[2 * fq]);
                    const u64 d0b = padd2(q0.y, ywn[2 * fq + 1]);
                    const u64 d1a = padd2(q1.x, ywn[2 * fq]);
                    const u64 d1b = padd2(q1.y, ywn[2 * fq + 1]);
                    float2 p;
                    p = unpack2(d0a); c0 += fabsf(p.x); c1 += fabsf(p.y);
                    p = unpack2(d0b); c2 += fabsf(p.x); c3 += fabsf(p.y);
                    p = unpack2(d1a); c4 += fabsf(p.x); c5 += fabsf(p.y);
                    p = unpack2(d1b); c6 += fabsf(p.x); c7 += fabsf(p.y);
                }
                rsum[l]     += (c0 + c1) + (c2 + c3);
                rsum[l + 1] += (c4 + c5) + (c6 + c7);
                rp += 2 * PADQ;
            }
        }

        // Compute epilogue: exp + direct stores + transpose staging.
        float* opd = out + (((size_t)(i * T_DIM + t) * V_DIM)
                            + (vg * 10 * 4 + n)) * V_DIM + j * 50 + wl;
        float* esp = e_s + wl * PADE + vg * 10;
        float dsum = 0.0f;
        #pragma unroll
        for (int l = 0; l < 10; l++) {
            const float e = __expf(rsum[l]);
            opd[(size_t)l * 4 * V_DIM] = e;
            if (!diag) esp[l] = e;
            dsum += e;
        }
        psum_s[vg * 50 + wl] = dsum;
    }
    __syncthreads();

    // Direct column partials: slab i, columns band j.
    if (tid < 50) {
        const float s = psum_s[tid] + psum_s[50 + tid] + psum_s[100 + tid] +
                        psum_s[150 + tid] + psum_s[200 + tid];
        g_psum[(((size_t)nt * 4 + i) * 4 + j) * 50 + tid] = s;
    }

    if (!diag) {
        // Transposed writes: slab j, row wl*4+n, col i*50+vl (coalesced).
        float* outj = out + ((size_t)(j * T_DIM + t) * V_DIM) * V_DIM;
        #pragma unroll
        for (int k = tid; k < 2500; k += 256) {
            const int rw = k / 50;             // wl
            const int cv = k % 50;             // vl
            outj[(size_t)(rw * 4 + n) * V_DIM + i * 50 + cv] =
                e_s[rw * PADE + cv];
        }
        // Transposed column partials: slab j, columns band i.
        if (tid < 50) {
            float s = 0.0f;
            #pragma unroll
            for (int rw = 0; rw < 50; rw++) s += e_s[rw * PADE + tid];
            g_psum[(((size_t)nt * 4 + j) * 4 + i) * 50 + tid] = s;
        }
    }
}

// ---------------------------------------------------------------------------
// Kernel 2: reduce partials -> g_sinv[ntp][w] = 1/colsum.  grid = 48 blocks.
// ---------------------------------------------------------------------------
__global__ void __launch_bounds__(256)
k_sums() {
    const int ntp = blockIdx.x;              // np*T + t
    const int np  = ntp / T_DIM;
    const int t   = ntp % T_DIM;
    const int tid = threadIdx.x;
    if (tid >= V_DIM) return;

    const int jw = tid / 50, wl = tid % 50;
    float s = 0.0f;
    #pragma unroll
    for (int n = 0; n < 4; n++) {
        s += g_psum[((((size_t)(n * T_DIM + t)) * 4 + np) * 4 + jw) * 50 + wl];
    }
    g_sinv[ntp * V_DIM + tid] = 1.0f / s;
}

// ---------------------------------------------------------------------------
// Kernel 3: streaming rescale. grid = (48, 20), block = 256.
// ---------------------------------------------------------------------------
__global__ void __launch_bounds__(256)
k_apply(float* __restrict__ out) {
    const int ntp   = blockIdx.x;
    const int chunk = blockIdx.y;
    const int tid   = threadIdx.x;

    const float4* si4 = reinterpret_cast<const float4*>(g_sinv) + ntp * 50;
    float4* o4 = reinterpret_cast<float4*>(out)
                 + (size_t)ntp * (V_DIM * V_DIM / 4) + (size_t)chunk * 500;

    #pragma unroll
    for (int jj = 0; jj < 2; jj++) {
        const int idx = tid + jj * 256;
        if (idx < 500) {
            float4 v = o4[idx];
            const float4 m = __ldg(&si4[idx % 50]);
            v.x *= m.x; v.y *= m.y; v.z *= m.z; v.w *= m.w;
            o4[idx] = v;
        }
    }
}

// ---------------------------------------------------------------------------

extern "C" void kernel_launch(void* const* d_in, const int* in_sizes, int n_in,
                              void* d_out, int out_size) {
    const float* x = (const float*)d_in[0];
    const float* a = (const float*)d_in[1];
    // Defensive input-order check: a has exactly F=64 elements.
    if (n_in >= 2 && in_sizes[0] == 64) {
        x = (const float*)d_in[1];
        a = (const float*)d_in[0];
    }
    float* out = (float*)d_out;

    // Smem: 2 padded bands + e_s tile + psum partials.
    const int smem_bytes =
        (2 * 50 * PADW + 50 * PADE + 250) * (int)sizeof(float);  // 39200
    cudaFuncSetAttribute(k_compute, cudaFuncAttributeMaxDynamicSharedMemorySize,
                         smem_bytes);

    dim3 g1(10, 48);                 // 480 tile-pair jobs
    k_compute<<<g1, 256, smem_bytes>>>(x, a, out);

    k_sums<<<48, 256>>>();

    dim3 g3(48, 20);                 // 960 blocks
    k_apply<<<g3, 256>>>(out);
}